// round 2
// baseline (speedup 1.0000x reference)
#include <cuda_runtime.h>

#define NROWS 204800
#define BN_EPS 1e-5f

#define FD0 100000
#define FD1 1000
#define FD2 100
#define FD3 50
#define PV (FD0 + FD1 + FD2 + FD3)
#define P_OFF1 (FD0 * 64)
#define P_OFF2 ((FD0 + FD1) * 64)
#define P_OFF3 ((FD0 + FD1 + FD2) * 64)

#define K1_BLOCKS 1024
#define K3_BLOCKS 1024
#define K5_BLOCKS 1024

// Scratch (device globals; no runtime allocation allowed)
__device__ float g_P[PV * 64];                    // precomputed emb_i @ w1_block_i^T
__device__ float g_A[64 * 8];                     // cont_w folded into w1
__device__ float g_cb[64];                        // b1 + cont_b folded into w1
__device__ float g_h1[(size_t)NROWS * 64];        // pre-BN layer-1 activations
__device__ float g_h2[(size_t)NROWS * 32];        // pre-BN layer-2 activations
__device__ float g_part1[K1_BLOCKS * 128];        // per-block BN1 partials (sum, sumsq)
__device__ float g_part2[K3_BLOCKS * 64];         // per-block BN2 partials
__device__ float g_bn1[128];                      // scale[64], shift[64]
__device__ float g_bn2[64];                       // scale[32], shift[32]

// ---------------------------------------------------------------------------
// Precompute P table: P[v][j] = sum_d emb[v,d] * w1[j, colOff + d]
// Warp per v-row; w1 column block held in registers per lane (2 output rows).
// ---------------------------------------------------------------------------
__global__ void __launch_bounds__(256) kP(const float* __restrict__ emb,
                                          const float* __restrict__ w1,
                                          int V, int pOff, int colOff) {
    int lane = threadIdx.x & 31;
    int gw = (blockIdx.x * blockDim.x + threadIdx.x) >> 5;
    int nw = (gridDim.x * blockDim.x) >> 5;
    float wa[32], wb[32];
#pragma unroll
    for (int d = 0; d < 32; d++) {
        wa[d] = w1[lane * 384 + colOff + d];
        wb[d] = w1[(lane + 32) * 384 + colOff + d];
    }
    for (int v = gw; v < V; v += nw) {
        float ev = emb[v * 32 + lane];
        float a0 = 0.f, a1 = 0.f;
#pragma unroll
        for (int d = 0; d < 32; d++) {
            float e = __shfl_sync(0xffffffffu, ev, d);
            a0 = fmaf(e, wa[d], a0);
            a1 = fmaf(e, wb[d], a1);
        }
        g_P[pOff + v * 64 + lane] = a0;
        g_P[pOff + v * 64 + 32 + lane] = a1;
    }
}

// ---------------------------------------------------------------------------
// Fold continuous features into w1: A[j][c] = cont_w[c,:] . w1[j, (4+c)*32:+32]
// g_cb[j] = b1[j] + sum_c cont_b[c,:] . w1[j, block c]
// ---------------------------------------------------------------------------
__global__ void kInit(const float* __restrict__ cont_w, const float* __restrict__ cont_b,
                      const float* __restrict__ w1, const float* __restrict__ b1) {
    int j = threadIdx.x;
    if (j < 64) {
        float cb = b1[j];
        for (int c = 0; c < 8; c++) {
            float a = 0.f;
#pragma unroll
            for (int d = 0; d < 32; d++) {
                float w = w1[j * 384 + (4 + c) * 32 + d];
                a = fmaf(cont_w[c * 32 + d], w, a);
                cb = fmaf(cont_b[c * 32 + d], w, cb);
            }
            g_A[j * 8 + c] = a;
        }
        g_cb[j] = cb;
    }
}

// ---------------------------------------------------------------------------
// Kernel 1: per row -> FM interaction + linear term (to out), pre-BN h1
// (via gathered P rows + xc @ A^T), and per-block BN1 sum/sumsq partials.
// Warp per row (lane = embedding dim d). 25 rows per warp.
// ---------------------------------------------------------------------------
__global__ void __launch_bounds__(256) k1(
    const float* __restrict__ x,
    const float* __restrict__ emb0, const float* __restrict__ emb1,
    const float* __restrict__ emb2, const float* __restrict__ emb3,
    const float* __restrict__ lin0, const float* __restrict__ lin1,
    const float* __restrict__ lin2, const float* __restrict__ lin3,
    const float* __restrict__ cont_w, const float* __restrict__ cont_b,
    const float* __restrict__ clin_w, const float* __restrict__ clin_b,
    const float* __restrict__ fin_bias,
    float* __restrict__ out) {
    int lane = threadIdx.x & 31;
    int warp = threadIdx.x >> 5;
    int gw = blockIdx.x * 8 + warp;
    const int nw = K1_BLOCKS * 8;

    float cw[8], cbv[8], clw[8], clb[8], A0[8], A1[8];
#pragma unroll
    for (int c = 0; c < 8; c++) {
        cw[c] = cont_w[c * 32 + lane];
        cbv[c] = cont_b[c * 32 + lane];
        clw[c] = clin_w[c * 32 + lane];
        clb[c] = clin_b[c * 32 + lane];
        A0[c] = g_A[lane * 8 + c];
        A1[c] = g_A[(lane + 32) * 8 + c];
    }
    float finb = fin_bias[lane];
    float cb0 = g_cb[lane], cb1 = g_cb[lane + 32];
    float sum0 = 0.f, sq0 = 0.f, sum1 = 0.f, sq1 = 0.f;

    for (int r = gw; r < NROWS; r += nw) {
        float xv = 0.f;
        if (lane < 12) xv = x[r * 12 + lane];
        int i0 = (int)__shfl_sync(0xffffffffu, xv, 0);
        int i1 = (int)__shfl_sync(0xffffffffu, xv, 1);
        int i2 = (int)__shfl_sync(0xffffffffu, xv, 2);
        int i3 = (int)__shfl_sync(0xffffffffu, xv, 3);
        float xc[8];
#pragma unroll
        for (int c = 0; c < 8; c++) xc[c] = __shfl_sync(0xffffffffu, xv, 4 + c);

        float e0 = emb0[i0 * 32 + lane];
        float e1 = emb1[i1 * 32 + lane];
        float e2 = emb2[i2 * 32 + lane];
        float e3 = emb3[i3 * 32 + lane];
        float s = e0 + e1 + e2 + e3;
        float sq = e0 * e0 + e1 * e1 + e2 * e2 + e3 * e3;
        float lin = finb + lin0[i0 * 32 + lane] + lin1[i1 * 32 + lane] +
                    lin2[i2 * 32 + lane] + lin3[i3 * 32 + lane];
#pragma unroll
        for (int c = 0; c < 8; c++) {
            float e = fmaf(xc[c], cw[c], cbv[c]);
            s += e;
            sq = fmaf(e, e, sq);
            lin += fmaf(xc[c], clw[c], clb[c]);
        }
        out[r * 32 + lane] = lin + 0.5f * (s * s - sq);

        float a0 = cb0 + g_P[i0 * 64 + lane] + g_P[P_OFF1 + i1 * 64 + lane] +
                   g_P[P_OFF2 + i2 * 64 + lane] + g_P[P_OFF3 + i3 * 64 + lane];
        float a1 = cb1 + g_P[i0 * 64 + 32 + lane] + g_P[P_OFF1 + i1 * 64 + 32 + lane] +
                   g_P[P_OFF2 + i2 * 64 + 32 + lane] + g_P[P_OFF3 + i3 * 64 + 32 + lane];
#pragma unroll
        for (int c = 0; c < 8; c++) {
            a0 = fmaf(xc[c], A0[c], a0);
            a1 = fmaf(xc[c], A1[c], a1);
        }
        g_h1[(size_t)r * 64 + lane] = a0;
        g_h1[(size_t)r * 64 + 32 + lane] = a1;
        sum0 += a0; sq0 = fmaf(a0, a0, sq0);
        sum1 += a1; sq1 = fmaf(a1, a1, sq1);
    }

    __shared__ float rs[64][8], rq[64][8];
    rs[lane][warp] = sum0; rs[lane + 32][warp] = sum1;
    rq[lane][warp] = sq0;  rq[lane + 32][warp] = sq1;
    __syncthreads();
    int t = threadIdx.x;
    if (t < 64) {
        float a = 0.f;
#pragma unroll
        for (int w = 0; w < 8; w++) a += rs[t][w];
        g_part1[blockIdx.x * 128 + t] = a;
    } else if (t < 128) {
        float a = 0.f;
#pragma unroll
        for (int w = 0; w < 8; w++) a += rq[t - 64][w];
        g_part1[blockIdx.x * 128 + t] = a;
    }
}

// ---------------------------------------------------------------------------
// Finalize BN1: reduce block partials deterministically, fold g/beta.
// ---------------------------------------------------------------------------
__global__ void __launch_bounds__(1024) k2(const float* __restrict__ g1,
                                           const float* __restrict__ beta1) {
    __shared__ float sm[1024];
    int t = threadIdx.x;
    int ch = t & 127;
    int sl = t >> 7;  // 8 slices
    float a = 0.f;
    for (int b = sl; b < K1_BLOCKS; b += 8) a += g_part1[b * 128 + ch];
    sm[t] = a;
    __syncthreads();
    if (t < 64) {
        float s = 0.f, q = 0.f;
#pragma unroll
        for (int i = 0; i < 8; i++) {
            s += sm[t + i * 128];
            q += sm[64 + t + i * 128];
        }
        float mean = s / (float)NROWS;
        float var = q / (float)NROWS - mean * mean;
        float scale = g1[t] * rsqrtf(var + BN_EPS);
        g_bn1[t] = scale;
        g_bn1[64 + t] = beta1[t] - mean * scale;
    }
}

// ---------------------------------------------------------------------------
// Kernel 3: h2 = relu(bn1(h1)) @ w2^T + b2 ; BN2 partials.
// Warp per row; w2 column (64 floats) register-resident per lane.
// ---------------------------------------------------------------------------
__global__ void __launch_bounds__(256) k3(const float* __restrict__ w2,
                                          const float* __restrict__ b2) {
    int lane = threadIdx.x & 31;
    int warp = threadIdx.x >> 5;
    int gw = blockIdx.x * 8 + warp;
    const int nw = K3_BLOCKS * 8;
    float wr[64];
#pragma unroll
    for (int k = 0; k < 64; k++) wr[k] = w2[lane * 64 + k];
    float sc0 = g_bn1[lane], sh0 = g_bn1[64 + lane];
    float sc1 = g_bn1[lane + 32], sh1 = g_bn1[96 + lane];
    float b2j = b2[lane];
    float sum = 0.f, sq = 0.f;

    for (int r = gw; r < NROWS; r += nw) {
        float a0 = fmaxf(fmaf(g_h1[(size_t)r * 64 + lane], sc0, sh0), 0.f);
        float a1 = fmaxf(fmaf(g_h1[(size_t)r * 64 + 32 + lane], sc1, sh1), 0.f);
        float acc = b2j;
#pragma unroll
        for (int k = 0; k < 32; k++)
            acc = fmaf(__shfl_sync(0xffffffffu, a0, k), wr[k], acc);
#pragma unroll
        for (int k = 0; k < 32; k++)
            acc = fmaf(__shfl_sync(0xffffffffu, a1, k), wr[32 + k], acc);
        g_h2[(size_t)r * 32 + lane] = acc;
        sum += acc;
        sq = fmaf(acc, acc, sq);
    }

    __shared__ float rs[32][8], rq[32][8];
    rs[lane][warp] = sum;
    rq[lane][warp] = sq;
    __syncthreads();
    int t = threadIdx.x;
    if (t < 32) {
        float a = 0.f;
#pragma unroll
        for (int w = 0; w < 8; w++) a += rs[t][w];
        g_part2[blockIdx.x * 64 + t] = a;
    } else if (t < 64) {
        float a = 0.f;
#pragma unroll
        for (int w = 0; w < 8; w++) a += rq[t - 32][w];
        g_part2[blockIdx.x * 64 + t] = a;
    }
}

// ---------------------------------------------------------------------------
// Finalize BN2.
// ---------------------------------------------------------------------------
__global__ void __launch_bounds__(1024) k4(const float* __restrict__ g2,
                                           const float* __restrict__ beta2) {
    __shared__ float sm[1024];
    int t = threadIdx.x;
    int ch = t & 63;
    int sl = t >> 6;  // 16 slices
    float a = 0.f;
    for (int b = sl; b < K3_BLOCKS; b += 16) a += g_part2[b * 64 + ch];
    sm[t] = a;
    __syncthreads();
    if (t < 32) {
        float s = 0.f, q = 0.f;
#pragma unroll
        for (int i = 0; i < 16; i++) {
            s += sm[t + i * 64];
            q += sm[32 + t + i * 64];
        }
        float mean = s / (float)NROWS;
        float var = q / (float)NROWS - mean * mean;
        float scale = g2[t] * rsqrtf(var + BN_EPS);
        g_bn2[t] = scale;
        g_bn2[32 + t] = beta2[t] - mean * scale;
    }
}

// ---------------------------------------------------------------------------
// Kernel 5: out += relu(bn2(h2)) @ w_out^T + b_out.
// ---------------------------------------------------------------------------
__global__ void __launch_bounds__(256) k5(const float* __restrict__ wout,
                                          const float* __restrict__ bout,
                                          float* __restrict__ out) {
    int lane = threadIdx.x & 31;
    int warp = threadIdx.x >> 5;
    int gw = blockIdx.x * 8 + warp;
    const int nw = K5_BLOCKS * 8;
    float wr[32];
#pragma unroll
    for (int k = 0; k < 32; k++) wr[k] = wout[lane * 32 + k];
    float sc = g_bn2[lane], sh = g_bn2[32 + lane];
    float bo = bout[lane];
    for (int r = gw; r < NROWS; r += nw) {
        float a = fmaxf(fmaf(g_h2[(size_t)r * 32 + lane], sc, sh), 0.f);
        float acc = bo;
#pragma unroll
        for (int k = 0; k < 32; k++)
            acc = fmaf(__shfl_sync(0xffffffffu, a, k), wr[k], acc);
        out[r * 32 + lane] += acc;
    }
}

// ---------------------------------------------------------------------------
// Input order follows setup_inputs() dict insertion order (metadata.txt):
//   x, emb0, lin0, emb1, lin1, emb2, lin2, emb3, lin3,
//   cont_w, cont_b, clin_w, clin_b, fin_bias,
//   w1, b1, g1, beta1, w2, b2, g2, beta2, w_out, b_out
// (emb/lin are INTERLEAVED because the python loop inserts emb{i} then lin{i})
// ---------------------------------------------------------------------------
extern "C" void kernel_launch(void* const* d_in, const int* in_sizes, int n_in,
                              void* d_out, int out_size) {
    const float* x      = (const float*)d_in[0];
    const float* emb0   = (const float*)d_in[1];
    const float* lin0   = (const float*)d_in[2];
    const float* emb1   = (const float*)d_in[3];
    const float* lin1   = (const float*)d_in[4];
    const float* emb2   = (const float*)d_in[5];
    const float* lin2   = (const float*)d_in[6];
    const float* emb3   = (const float*)d_in[7];
    const float* lin3   = (const float*)d_in[8];
    const float* cont_w = (const float*)d_in[9];
    const float* cont_b = (const float*)d_in[10];
    const float* clin_w = (const float*)d_in[11];
    const float* clin_b = (const float*)d_in[12];
    const float* fin_b  = (const float*)d_in[13];
    const float* w1     = (const float*)d_in[14];
    const float* b1     = (const float*)d_in[15];
    const float* g1     = (const float*)d_in[16];
    const float* beta1  = (const float*)d_in[17];
    const float* w2     = (const float*)d_in[18];
    const float* b2     = (const float*)d_in[19];
    const float* g2     = (const float*)d_in[20];
    const float* beta2  = (const float*)d_in[21];
    const float* w_out  = (const float*)d_in[22];
    const float* b_out  = (const float*)d_in[23];
    float* out = (float*)d_out;

    kInit<<<1, 64>>>(cont_w, cont_b, w1, b1);
    kP<<<512, 256>>>(emb0, w1, FD0, 0, 0);
    kP<<<8, 256>>>(emb1, w1, FD1, P_OFF1, 32);
    kP<<<1, 256>>>(emb2, w1, FD2, P_OFF2, 64);
    kP<<<1, 256>>>(emb3, w1, FD3, P_OFF3, 96);
    k1<<<K1_BLOCKS, 256>>>(x, emb0, emb1, emb2, emb3, lin0, lin1, lin2, lin3,
                           cont_w, cont_b, clin_w, clin_b, fin_b, out);
    k2<<<1, 1024>>>(g1, beta1);
    k3<<<K3_BLOCKS, 256>>>(w2, b2);
    k4<<<1, 1024>>>(g2, beta2);
    k5<<<K5_BLOCKS, 256>>>(w_out, b_out, out);
}

// round 3
// speedup vs baseline: 1.0982x; 1.0982x over previous
#include <cuda_runtime.h>

#define NROWS 204800
#define BN_EPS 1e-5f

#define FD0 100000
#define FD1 1000
#define FD2 100
#define FD3 50
#define PV (FD0 + FD1 + FD2 + FD3)
#define P_OFF1 (FD0 * 64)
#define P_OFF2 ((FD0 + FD1) * 64)
#define P_OFF3 ((FD0 + FD1 + FD2) * 64)

#define K1_BLOCKS 1024
#define K3_BLOCKS 1024
#define K5_BLOCKS 1024
#define SETUP_BLOCKS 512

// Scratch (device globals; no runtime allocation allowed)
__device__ float g_P[PV * 64];                    // precomputed emb_i @ w1_block_i^T
__device__ float g_A[64 * 8];                     // cont_w folded into w1
__device__ float g_cb[64];                        // b1 + cont_b folded into w1
__device__ float g_h1[(size_t)NROWS * 64];        // pre-BN layer-1 activations
__device__ float g_h2[(size_t)NROWS * 32];        // pre-BN layer-2 activations
__device__ float g_part1[K1_BLOCKS * 128];        // per-block BN1 partials (sum, sumsq)
__device__ float g_part2[K3_BLOCKS * 64];         // per-block BN2 partials
__device__ float g_bn1[128];                      // scale[64], shift[64]
__device__ float g_bn2[64];                       // scale[32], shift[32]
__device__ unsigned g_cnt1 = 0;                   // ticket counter, k1 finalize
__device__ unsigned g_cnt2 = 0;                   // ticket counter, k3 finalize

// ---------------------------------------------------------------------------
// kSetup: one launch covering the cont-fold init AND all four P tables.
//   blocks [0,506)   -> table 0 (emb0, 100000 rows)
//   blocks [506,510) -> table 1 (emb1, 1000 rows)
//   block  510       -> warps 0-3 table 2 (100), warps 4-7 table 3 (50)
//   block  511       -> kInit fold (64 threads)
// P[v][j] = sum_d emb[v,d] * w1[j, colOff + d]; warp per v-row,
// w1 column block register-resident (2 output rows per lane).
// ---------------------------------------------------------------------------
__global__ void __launch_bounds__(256) kSetup(
    const float* __restrict__ emb0, const float* __restrict__ emb1,
    const float* __restrict__ emb2, const float* __restrict__ emb3,
    const float* __restrict__ w1, const float* __restrict__ b1,
    const float* __restrict__ cont_w, const float* __restrict__ cont_b) {
    int bid = blockIdx.x;
    int lane = threadIdx.x & 31;
    int warp = threadIdx.x >> 5;

    if (bid == 511) {  // cont-feature fold into w1
        int j = threadIdx.x;
        if (j < 64) {
            float cb = b1[j];
            for (int c = 0; c < 8; c++) {
                float a = 0.f;
#pragma unroll
                for (int d = 0; d < 32; d++) {
                    float w = w1[j * 384 + (4 + c) * 32 + d];
                    a = fmaf(cont_w[c * 32 + d], w, a);
                    cb = fmaf(cont_b[c * 32 + d], w, cb);
                }
                g_A[j * 8 + c] = a;
            }
            g_cb[j] = cb;
        }
        return;
    }

    const float* emb;
    int V, pOff, colOff, wfirst, nwarp;
    if (bid < 506) {
        emb = emb0; V = FD0; pOff = 0; colOff = 0;
        wfirst = bid * 8 + warp; nwarp = 506 * 8;
    } else if (bid < 510) {
        emb = emb1; V = FD1; pOff = P_OFF1; colOff = 32;
        wfirst = (bid - 506) * 8 + warp; nwarp = 32;
    } else if (warp < 4) {
        emb = emb2; V = FD2; pOff = P_OFF2; colOff = 64;
        wfirst = warp; nwarp = 4;
    } else {
        emb = emb3; V = FD3; pOff = P_OFF3; colOff = 96;
        wfirst = warp - 4; nwarp = 4;
    }

    float wa[32], wb[32];
#pragma unroll
    for (int d = 0; d < 32; d++) {
        wa[d] = w1[lane * 384 + colOff + d];
        wb[d] = w1[(lane + 32) * 384 + colOff + d];
    }
    for (int v = wfirst; v < V; v += nwarp) {
        float ev = emb[v * 32 + lane];
        float a0 = 0.f, a1 = 0.f;
#pragma unroll
        for (int d = 0; d < 32; d++) {
            float e = __shfl_sync(0xffffffffu, ev, d);
            a0 = fmaf(e, wa[d], a0);
            a1 = fmaf(e, wb[d], a1);
        }
        g_P[pOff + v * 64 + lane] = a0;
        g_P[pOff + v * 64 + 32 + lane] = a1;
    }
}

// ---------------------------------------------------------------------------
// Kernel 1: per row -> FM interaction + linear term (to out), pre-BN h1
// (via gathered P rows + xc @ A^T), per-block BN1 partials, and the
// LAST block finalizes BN1 (threadfence-reduction) -> g_bn1.
// ---------------------------------------------------------------------------
__global__ void __launch_bounds__(256) k1(
    const float* __restrict__ x,
    const float* __restrict__ emb0, const float* __restrict__ emb1,
    const float* __restrict__ emb2, const float* __restrict__ emb3,
    const float* __restrict__ lin0, const float* __restrict__ lin1,
    const float* __restrict__ lin2, const float* __restrict__ lin3,
    const float* __restrict__ cont_w, const float* __restrict__ cont_b,
    const float* __restrict__ clin_w, const float* __restrict__ clin_b,
    const float* __restrict__ fin_bias,
    const float* __restrict__ g1, const float* __restrict__ beta1,
    float* __restrict__ out) {
    int lane = threadIdx.x & 31;
    int warp = threadIdx.x >> 5;
    int gw = blockIdx.x * 8 + warp;
    const int nw = K1_BLOCKS * 8;

    float cw[8], cbv[8], clw[8], clb[8], A0[8], A1[8];
#pragma unroll
    for (int c = 0; c < 8; c++) {
        cw[c] = cont_w[c * 32 + lane];
        cbv[c] = cont_b[c * 32 + lane];
        clw[c] = clin_w[c * 32 + lane];
        clb[c] = clin_b[c * 32 + lane];
        A0[c] = g_A[lane * 8 + c];
        A1[c] = g_A[(lane + 32) * 8 + c];
    }
    float finb = fin_bias[lane];
    float cb0 = g_cb[lane], cb1 = g_cb[lane + 32];
    float sum0 = 0.f, sq0 = 0.f, sum1 = 0.f, sq1 = 0.f;

    for (int r = gw; r < NROWS; r += nw) {
        float xv = 0.f;
        if (lane < 12) xv = x[r * 12 + lane];
        int i0 = (int)__shfl_sync(0xffffffffu, xv, 0);
        int i1 = (int)__shfl_sync(0xffffffffu, xv, 1);
        int i2 = (int)__shfl_sync(0xffffffffu, xv, 2);
        int i3 = (int)__shfl_sync(0xffffffffu, xv, 3);
        float xc[8];
#pragma unroll
        for (int c = 0; c < 8; c++) xc[c] = __shfl_sync(0xffffffffu, xv, 4 + c);

        float e0 = emb0[i0 * 32 + lane];
        float e1 = emb1[i1 * 32 + lane];
        float e2 = emb2[i2 * 32 + lane];
        float e3 = emb3[i3 * 32 + lane];
        float s = e0 + e1 + e2 + e3;
        float sq = e0 * e0 + e1 * e1 + e2 * e2 + e3 * e3;
        float lin = finb + lin0[i0 * 32 + lane] + lin1[i1 * 32 + lane] +
                    lin2[i2 * 32 + lane] + lin3[i3 * 32 + lane];
#pragma unroll
        for (int c = 0; c < 8; c++) {
            float e = fmaf(xc[c], cw[c], cbv[c]);
            s += e;
            sq = fmaf(e, e, sq);
            lin += fmaf(xc[c], clw[c], clb[c]);
        }
        out[r * 32 + lane] = lin + 0.5f * (s * s - sq);

        float a0 = cb0 + g_P[i0 * 64 + lane] + g_P[P_OFF1 + i1 * 64 + lane] +
                   g_P[P_OFF2 + i2 * 64 + lane] + g_P[P_OFF3 + i3 * 64 + lane];
        float a1 = cb1 + g_P[i0 * 64 + 32 + lane] + g_P[P_OFF1 + i1 * 64 + 32 + lane] +
                   g_P[P_OFF2 + i2 * 64 + 32 + lane] + g_P[P_OFF3 + i3 * 64 + 32 + lane];
#pragma unroll
        for (int c = 0; c < 8; c++) {
            a0 = fmaf(xc[c], A0[c], a0);
            a1 = fmaf(xc[c], A1[c], a1);
        }
        g_h1[(size_t)r * 64 + lane] = a0;
        g_h1[(size_t)r * 64 + 32 + lane] = a1;
        sum0 += a0; sq0 = fmaf(a0, a0, sq0);
        sum1 += a1; sq1 = fmaf(a1, a1, sq1);
    }

    __shared__ float rs[64][8], rq[64][8];
    rs[lane][warp] = sum0; rs[lane + 32][warp] = sum1;
    rq[lane][warp] = sq0;  rq[lane + 32][warp] = sq1;
    __syncthreads();
    int t = threadIdx.x;
    if (t < 64) {
        float a = 0.f;
#pragma unroll
        for (int w = 0; w < 8; w++) a += rs[t][w];
        g_part1[blockIdx.x * 128 + t] = a;
    } else if (t < 128) {
        float a = 0.f;
#pragma unroll
        for (int w = 0; w < 8; w++) a += rq[t - 64][w];
        g_part1[blockIdx.x * 128 + t] = a;
    }

    // --- threadfence-reduction finalize (last block computes BN1) ---
    __threadfence();
    __shared__ unsigned s_last;
    if (t == 0) {
        unsigned tk = atomicAdd(&g_cnt1, 1u);
        s_last = (tk == gridDim.x - 1) ? 1u : 0u;
    }
    __syncthreads();
    if (s_last) {
        __shared__ float sm[256];
        int ch = t & 127;
        int half = t >> 7;  // 2 slices of 512 blocks
        float a = 0.f;
        int b0 = half * (K1_BLOCKS / 2);
        for (int b = b0; b < b0 + K1_BLOCKS / 2; b++) a += g_part1[b * 128 + ch];
        sm[t] = a;
        __syncthreads();
        if (t < 64) {
            float s = sm[t] + sm[128 + t];
            float q = sm[64 + t] + sm[192 + t];
            float mean = s / (float)NROWS;
            float var = q / (float)NROWS - mean * mean;
            float scale = g1[t] * rsqrtf(var + BN_EPS);
            g_bn1[t] = scale;
            g_bn1[64 + t] = beta1[t] - mean * scale;
        }
        if (t == 0) g_cnt1 = 0;  // reset for next graph replay
    }
}

// ---------------------------------------------------------------------------
// Kernel 3: h2 = relu(bn1(h1)) @ w2^T + b2 ; BN2 partials; last block
// finalizes BN2 -> g_bn2. Warp per row; w2 column register-resident.
// ---------------------------------------------------------------------------
__global__ void __launch_bounds__(256) k3(const float* __restrict__ w2,
                                          const float* __restrict__ b2,
                                          const float* __restrict__ g2,
                                          const float* __restrict__ beta2) {
    int lane = threadIdx.x & 31;
    int warp = threadIdx.x >> 5;
    int gw = blockIdx.x * 8 + warp;
    const int nw = K3_BLOCKS * 8;
    float wr[64];
#pragma unroll
    for (int k = 0; k < 64; k++) wr[k] = w2[lane * 64 + k];
    float sc0 = g_bn1[lane], sh0 = g_bn1[64 + lane];
    float sc1 = g_bn1[lane + 32], sh1 = g_bn1[96 + lane];
    float b2j = b2[lane];
    float sum = 0.f, sq = 0.f;

    for (int r = gw; r < NROWS; r += nw) {
        float a0 = fmaxf(fmaf(g_h1[(size_t)r * 64 + lane], sc0, sh0), 0.f);
        float a1 = fmaxf(fmaf(g_h1[(size_t)r * 64 + 32 + lane], sc1, sh1), 0.f);
        // 4 independent accumulator chains (16 deep each)
        float c0 = b2j, c1 = 0.f, c2 = 0.f, c3 = 0.f;
#pragma unroll
        for (int k = 0; k < 16; k++) {
            c0 = fmaf(__shfl_sync(0xffffffffu, a0, k), wr[k], c0);
            c1 = fmaf(__shfl_sync(0xffffffffu, a0, k + 16), wr[k + 16], c1);
            c2 = fmaf(__shfl_sync(0xffffffffu, a1, k), wr[k + 32], c2);
            c3 = fmaf(__shfl_sync(0xffffffffu, a1, k + 16), wr[k + 48], c3);
        }
        float acc = (c0 + c1) + (c2 + c3);
        g_h2[(size_t)r * 32 + lane] = acc;
        sum += acc;
        sq = fmaf(acc, acc, sq);
    }

    __shared__ float rs[32][8], rq[32][8];
    rs[lane][warp] = sum;
    rq[lane][warp] = sq;
    __syncthreads();
    int t = threadIdx.x;
    if (t < 32) {
        float a = 0.f;
#pragma unroll
        for (int w = 0; w < 8; w++) a += rs[t][w];
        g_part2[blockIdx.x * 64 + t] = a;
    } else if (t < 64) {
        float a = 0.f;
#pragma unroll
        for (int w = 0; w < 8; w++) a += rq[t - 32][w];
        g_part2[blockIdx.x * 64 + t] = a;
    }

    // --- threadfence-reduction finalize (last block computes BN2) ---
    __threadfence();
    __shared__ unsigned s_last;
    if (t == 0) {
        unsigned tk = atomicAdd(&g_cnt2, 1u);
        s_last = (tk == gridDim.x - 1) ? 1u : 0u;
    }
    __syncthreads();
    if (s_last) {
        __shared__ float sm[256];
        int ch = t & 63;
        int sl = t >> 6;  // 4 slices of 256 blocks
        float a = 0.f;
        int b0 = sl * (K3_BLOCKS / 4);
        for (int b = b0; b < b0 + K3_BLOCKS / 4; b++) a += g_part2[b * 64 + ch];
        sm[t] = a;
        __syncthreads();
        if (t < 32) {
            float s = (sm[t] + sm[64 + t]) + (sm[128 + t] + sm[192 + t]);
            float q = (sm[32 + t] + sm[96 + t]) + (sm[160 + t] + sm[224 + t]);
            float mean = s / (float)NROWS;
            float var = q / (float)NROWS - mean * mean;
            float scale = g2[t] * rsqrtf(var + BN_EPS);
            g_bn2[t] = scale;
            g_bn2[32 + t] = beta2[t] - mean * scale;
        }
        if (t == 0) g_cnt2 = 0;  // reset for next graph replay
    }
}

// ---------------------------------------------------------------------------
// Kernel 5: out += relu(bn2(h2)) @ w_out^T + b_out.
// ---------------------------------------------------------------------------
__global__ void __launch_bounds__(256) k5(const float* __restrict__ wout,
                                          const float* __restrict__ bout,
                                          float* __restrict__ out) {
    int lane = threadIdx.x & 31;
    int warp = threadIdx.x >> 5;
    int gw = blockIdx.x * 8 + warp;
    const int nw = K5_BLOCKS * 8;
    float wr[32];
#pragma unroll
    for (int k = 0; k < 32; k++) wr[k] = wout[lane * 32 + k];
    float sc = g_bn2[lane], sh = g_bn2[32 + lane];
    float bo = bout[lane];
    for (int r = gw; r < NROWS; r += nw) {
        float a = fmaxf(fmaf(g_h2[(size_t)r * 32 + lane], sc, sh), 0.f);
        float c0 = bo, c1 = 0.f;
#pragma unroll
        for (int k = 0; k < 16; k++) {
            c0 = fmaf(__shfl_sync(0xffffffffu, a, k), wr[k], c0);
            c1 = fmaf(__shfl_sync(0xffffffffu, a, k + 16), wr[k + 16], c1);
        }
        out[r * 32 + lane] += c0 + c1;
    }
}

// ---------------------------------------------------------------------------
// Input order follows setup_inputs() dict insertion order (metadata.txt):
//   x, emb0, lin0, emb1, lin1, emb2, lin2, emb3, lin3,
//   cont_w, cont_b, clin_w, clin_b, fin_bias,
//   w1, b1, g1, beta1, w2, b2, g2, beta2, w_out, b_out
// ---------------------------------------------------------------------------
extern "C" void kernel_launch(void* const* d_in, const int* in_sizes, int n_in,
                              void* d_out, int out_size) {
    const float* x      = (const float*)d_in[0];
    const float* emb0   = (const float*)d_in[1];
    const float* lin0   = (const float*)d_in[2];
    const float* emb1   = (const float*)d_in[3];
    const float* lin1   = (const float*)d_in[4];
    const float* emb2   = (const float*)d_in[5];
    const float* lin2   = (const float*)d_in[6];
    const float* emb3   = (const float*)d_in[7];
    const float* lin3   = (const float*)d_in[8];
    const float* cont_w = (const float*)d_in[9];
    const float* cont_b = (const float*)d_in[10];
    const float* clin_w = (const float*)d_in[11];
    const float* clin_b = (const float*)d_in[12];
    const float* fin_b  = (const float*)d_in[13];
    const float* w1     = (const float*)d_in[14];
    const float* b1     = (const float*)d_in[15];
    const float* g1     = (const float*)d_in[16];
    const float* beta1  = (const float*)d_in[17];
    const float* w2     = (const float*)d_in[18];
    const float* b2     = (const float*)d_in[19];
    const float* g2     = (const float*)d_in[20];
    const float* beta2  = (const float*)d_in[21];
    const float* w_out  = (const float*)d_in[22];
    const float* b_out  = (const float*)d_in[23];
    float* out = (float*)d_out;

    kSetup<<<SETUP_BLOCKS, 256>>>(emb0, emb1, emb2, emb3, w1, b1, cont_w, cont_b);
    k1<<<K1_BLOCKS, 256>>>(x, emb0, emb1, emb2, emb3, lin0, lin1, lin2, lin3,
                           cont_w, cont_b, clin_w, clin_b, fin_b, g1, beta1, out);
    k3<<<K3_BLOCKS, 256>>>(w2, b2, g2, beta2);
    k5<<<K5_BLOCKS, 256>>>(w_out, b_out, out);
}

// round 4
// speedup vs baseline: 2.2124x; 2.0146x over previous
#include <cuda_runtime.h>

#define NROWS 204800
#define BN_EPS 1e-5f

#define FD0 100000
#define FD1 1000
#define FD2 100
#define FD3 50
#define PV (FD0 + FD1 + FD2 + FD3)
#define P_OFF1 (FD0 * 64)
#define P_OFF2 ((FD0 + FD1) * 64)
#define P_OFF3 ((FD0 + FD1 + FD2) * 64)

#define K1_BLOCKS 1024
#define K3_GRID 592
#define K5_GRID 592
#define SETUP_BLOCKS 512
#define TILE_R 128
#define N_TILES (NROWS / TILE_R)   // 1600

// Scratch (device globals; no runtime allocation allowed)
__device__ float g_P[PV * 64];                    // precomputed emb_i @ w1_block_i^T
__device__ float g_A[64 * 8];                     // cont_w folded into w1
__device__ float g_cb[64];                        // b1 + cont_b folded into w1
__device__ float g_h1[(size_t)NROWS * 64];        // pre-BN layer-1 activations
__device__ float g_h2[(size_t)NROWS * 32];        // pre-BN layer-2 activations
__device__ float g_part1[K1_BLOCKS * 128];        // per-block BN1 partials
__device__ float g_part2[K3_GRID * 64];           // per-block BN2 partials
__device__ float g_bn1[128];                      // scale[64], shift[64]
__device__ float g_bn2[64];                       // scale[32], shift[32]
__device__ unsigned g_cnt1 = 0;
__device__ unsigned g_cnt2 = 0;

// ---------------------------------------------------------------------------
// kSetup: cont-fold init AND all four P tables in one launch.
// ---------------------------------------------------------------------------
__global__ void __launch_bounds__(256) kSetup(
    const float* __restrict__ emb0, const float* __restrict__ emb1,
    const float* __restrict__ emb2, const float* __restrict__ emb3,
    const float* __restrict__ w1, const float* __restrict__ b1,
    const float* __restrict__ cont_w, const float* __restrict__ cont_b) {
    int bid = blockIdx.x;
    int lane = threadIdx.x & 31;
    int warp = threadIdx.x >> 5;

    if (bid == 511) {  // cont-feature fold into w1
        int j = threadIdx.x;
        if (j < 64) {
            float cb = b1[j];
            for (int c = 0; c < 8; c++) {
                float a = 0.f;
#pragma unroll
                for (int d = 0; d < 32; d++) {
                    float w = w1[j * 384 + (4 + c) * 32 + d];
                    a = fmaf(cont_w[c * 32 + d], w, a);
                    cb = fmaf(cont_b[c * 32 + d], w, cb);
                }
                g_A[j * 8 + c] = a;
            }
            g_cb[j] = cb;
        }
        return;
    }

    const float* emb;
    int V, pOff, colOff, wfirst, nwarp;
    if (bid < 506) {
        emb = emb0; V = FD0; pOff = 0; colOff = 0;
        wfirst = bid * 8 + warp; nwarp = 506 * 8;
    } else if (bid < 510) {
        emb = emb1; V = FD1; pOff = P_OFF1; colOff = 32;
        wfirst = (bid - 506) * 8 + warp; nwarp = 32;
    } else if (warp < 4) {
        emb = emb2; V = FD2; pOff = P_OFF2; colOff = 64;
        wfirst = warp; nwarp = 4;
    } else {
        emb = emb3; V = FD3; pOff = P_OFF3; colOff = 96;
        wfirst = warp - 4; nwarp = 4;
    }

    float wa[32], wb[32];
#pragma unroll
    for (int d = 0; d < 32; d++) {
        wa[d] = w1[lane * 384 + colOff + d];
        wb[d] = w1[(lane + 32) * 384 + colOff + d];
    }
    for (int v = wfirst; v < V; v += nwarp) {
        float ev = emb[v * 32 + lane];
        float a0 = 0.f, a1 = 0.f;
#pragma unroll
        for (int d = 0; d < 32; d++) {
            float e = __shfl_sync(0xffffffffu, ev, d);
            a0 = fmaf(e, wa[d], a0);
            a1 = fmaf(e, wb[d], a1);
        }
        g_P[pOff + v * 64 + lane] = a0;
        g_P[pOff + v * 64 + 32 + lane] = a1;
    }
}

// ---------------------------------------------------------------------------
// Kernel 1: 2 rows per warp iteration (doubled gather MLP).
// FM interaction + linear -> out; h1 -> g_h1; BN1 partials; last block
// finalizes BN1.
// ---------------------------------------------------------------------------
__global__ void __launch_bounds__(256) k1(
    const float* __restrict__ x,
    const float* __restrict__ emb0, const float* __restrict__ emb1,
    const float* __restrict__ emb2, const float* __restrict__ emb3,
    const float* __restrict__ lin0, const float* __restrict__ lin1,
    const float* __restrict__ lin2, const float* __restrict__ lin3,
    const float* __restrict__ cont_w, const float* __restrict__ cont_b,
    const float* __restrict__ clin_w, const float* __restrict__ clin_b,
    const float* __restrict__ fin_bias,
    const float* __restrict__ g1, const float* __restrict__ beta1,
    float* __restrict__ out) {
    int lane = threadIdx.x & 31;
    int warp = threadIdx.x >> 5;
    int gw = blockIdx.x * 8 + warp;
    const int nw = K1_BLOCKS * 8;
    const int NPAIR = NROWS / 2;

    float cw[8], cbv[8], clw[8], clb[8], A0[8], A1[8];
#pragma unroll
    for (int c = 0; c < 8; c++) {
        cw[c] = cont_w[c * 32 + lane];
        cbv[c] = cont_b[c * 32 + lane];
        clw[c] = clin_w[c * 32 + lane];
        clb[c] = clin_b[c * 32 + lane];
        A0[c] = g_A[lane * 8 + c];
        A1[c] = g_A[(lane + 32) * 8 + c];
    }
    float finb = fin_bias[lane];
    float cb0 = g_cb[lane], cb1 = g_cb[lane + 32];
    float sum0 = 0.f, sq0 = 0.f, sum1 = 0.f, sq1 = 0.f;

    for (int pr = gw; pr < NPAIR; pr += nw) {
        int rA = pr * 2;
        int rB = rA + 1;
        float xv = 0.f;
        if (lane < 24) xv = x[rA * 12 + lane];
        int iA0 = (int)__shfl_sync(0xffffffffu, xv, 0);
        int iA1 = (int)__shfl_sync(0xffffffffu, xv, 1);
        int iA2 = (int)__shfl_sync(0xffffffffu, xv, 2);
        int iA3 = (int)__shfl_sync(0xffffffffu, xv, 3);
        int iB0 = (int)__shfl_sync(0xffffffffu, xv, 12);
        int iB1 = (int)__shfl_sync(0xffffffffu, xv, 13);
        int iB2 = (int)__shfl_sync(0xffffffffu, xv, 14);
        int iB3 = (int)__shfl_sync(0xffffffffu, xv, 15);
        float xcA[8], xcB[8];
#pragma unroll
        for (int c = 0; c < 8; c++) {
            xcA[c] = __shfl_sync(0xffffffffu, xv, 4 + c);
            xcB[c] = __shfl_sync(0xffffffffu, xv, 16 + c);
        }

        // issue all gathers (16 independent loads)
        float eA0 = emb0[iA0 * 32 + lane], eB0 = emb0[iB0 * 32 + lane];
        float eA1 = emb1[iA1 * 32 + lane], eB1 = emb1[iB1 * 32 + lane];
        float eA2 = emb2[iA2 * 32 + lane], eB2 = emb2[iB2 * 32 + lane];
        float eA3 = emb3[iA3 * 32 + lane], eB3 = emb3[iB3 * 32 + lane];
        float lA = finb + lin0[iA0 * 32 + lane] + lin1[iA1 * 32 + lane] +
                   lin2[iA2 * 32 + lane] + lin3[iA3 * 32 + lane];
        float lB = finb + lin0[iB0 * 32 + lane] + lin1[iB1 * 32 + lane] +
                   lin2[iB2 * 32 + lane] + lin3[iB3 * 32 + lane];
        float pA0a = g_P[iA0 * 64 + lane],        pA0b = g_P[iA0 * 64 + 32 + lane];
        float pA1a = g_P[P_OFF1 + iA1 * 64 + lane], pA1b = g_P[P_OFF1 + iA1 * 64 + 32 + lane];
        float pA2a = g_P[P_OFF2 + iA2 * 64 + lane], pA2b = g_P[P_OFF2 + iA2 * 64 + 32 + lane];
        float pA3a = g_P[P_OFF3 + iA3 * 64 + lane], pA3b = g_P[P_OFF3 + iA3 * 64 + 32 + lane];
        float pB0a = g_P[iB0 * 64 + lane],        pB0b = g_P[iB0 * 64 + 32 + lane];
        float pB1a = g_P[P_OFF1 + iB1 * 64 + lane], pB1b = g_P[P_OFF1 + iB1 * 64 + 32 + lane];
        float pB2a = g_P[P_OFF2 + iB2 * 64 + lane], pB2b = g_P[P_OFF2 + iB2 * 64 + 32 + lane];
        float pB3a = g_P[P_OFF3 + iB3 * 64 + lane], pB3b = g_P[P_OFF3 + iB3 * 64 + 32 + lane];

        // row A
        {
            float s = eA0 + eA1 + eA2 + eA3;
            float sq = eA0 * eA0 + eA1 * eA1 + eA2 * eA2 + eA3 * eA3;
            float lin = lA;
#pragma unroll
            for (int c = 0; c < 8; c++) {
                float e = fmaf(xcA[c], cw[c], cbv[c]);
                s += e;
                sq = fmaf(e, e, sq);
                lin += fmaf(xcA[c], clw[c], clb[c]);
            }
            out[rA * 32 + lane] = lin + 0.5f * (s * s - sq);
            float a0 = cb0 + pA0a + pA1a + pA2a + pA3a;
            float a1 = cb1 + pA0b + pA1b + pA2b + pA3b;
#pragma unroll
            for (int c = 0; c < 8; c++) {
                a0 = fmaf(xcA[c], A0[c], a0);
                a1 = fmaf(xcA[c], A1[c], a1);
            }
            g_h1[(size_t)rA * 64 + lane] = a0;
            g_h1[(size_t)rA * 64 + 32 + lane] = a1;
            sum0 += a0; sq0 = fmaf(a0, a0, sq0);
            sum1 += a1; sq1 = fmaf(a1, a1, sq1);
        }
        // row B
        {
            float s = eB0 + eB1 + eB2 + eB3;
            float sq = eB0 * eB0 + eB1 * eB1 + eB2 * eB2 + eB3 * eB3;
            float lin = lB;
#pragma unroll
            for (int c = 0; c < 8; c++) {
                float e = fmaf(xcB[c], cw[c], cbv[c]);
                s += e;
                sq = fmaf(e, e, sq);
                lin += fmaf(xcB[c], clw[c], clb[c]);
            }
            out[rB * 32 + lane] = lin + 0.5f * (s * s - sq);
            float a0 = cb0 + pB0a + pB1a + pB2a + pB3a;
            float a1 = cb1 + pB0b + pB1b + pB2b + pB3b;
#pragma unroll
            for (int c = 0; c < 8; c++) {
                a0 = fmaf(xcB[c], A0[c], a0);
                a1 = fmaf(xcB[c], A1[c], a1);
            }
            g_h1[(size_t)rB * 64 + lane] = a0;
            g_h1[(size_t)rB * 64 + 32 + lane] = a1;
            sum0 += a0; sq0 = fmaf(a0, a0, sq0);
            sum1 += a1; sq1 = fmaf(a1, a1, sq1);
        }
    }

    __shared__ float rs[64][8], rq[64][8];
    rs[lane][warp] = sum0; rs[lane + 32][warp] = sum1;
    rq[lane][warp] = sq0;  rq[lane + 32][warp] = sq1;
    __syncthreads();
    int t = threadIdx.x;
    if (t < 64) {
        float a = 0.f;
#pragma unroll
        for (int w = 0; w < 8; w++) a += rs[t][w];
        g_part1[blockIdx.x * 128 + t] = a;
    } else if (t < 128) {
        float a = 0.f;
#pragma unroll
        for (int w = 0; w < 8; w++) a += rq[t - 64][w];
        g_part1[blockIdx.x * 128 + t] = a;
    }

    __threadfence();
    __shared__ unsigned s_last;
    if (t == 0) {
        unsigned tk = atomicAdd(&g_cnt1, 1u);
        s_last = (tk == gridDim.x - 1) ? 1u : 0u;
    }
    __syncthreads();
    if (s_last) {
        __shared__ float sm[256];
        int ch = t & 127;
        int half = t >> 7;
        float a = 0.f;
        int b0 = half * (K1_BLOCKS / 2);
        for (int b = b0; b < b0 + K1_BLOCKS / 2; b++) a += g_part1[b * 128 + ch];
        sm[t] = a;
        __syncthreads();
        if (t < 64) {
            float s = sm[t] + sm[128 + t];
            float q = sm[64 + t] + sm[192 + t];
            float mean = s / (float)NROWS;
            float var = q / (float)NROWS - mean * mean;
            float scale = g1[t] * rsqrtf(var + BN_EPS);
            g_bn1[t] = scale;
            g_bn1[64 + t] = beta1[t] - mean * scale;
        }
        if (t == 0) g_cnt1 = 0;
    }
}

// ---------------------------------------------------------------------------
// Kernel 3: smem-tiled GEMM. h2 = relu(bn1(h1)) @ w2^T + b2.
// 128-row tiles; thread computes 4 rows x 4 cols via float4 LDS.
// BN2 partials in registers across tiles; deterministic reduction.
// ---------------------------------------------------------------------------
__global__ void __launch_bounds__(256) k3(const float* __restrict__ w2,
                                          const float* __restrict__ b2,
                                          const float* __restrict__ g2,
                                          const float* __restrict__ beta2) {
    __shared__ float a[TILE_R * 68];     // bn+relu(h1) tile, stride 68
    __shared__ float wt[64 * 36];        // w2 transposed: wt[k*36+j]
    __shared__ float sc[64], sh[64];
    __shared__ float wsum[8 * 32], wsq[8 * 32];

    int tid = threadIdx.x;
    int lane = tid & 31, warp = tid >> 5;
    int tr = lane >> 3, tj = lane & 7;
    int j0 = tj * 4;

    // preamble: stage w2^T (coalesced read, strided smem store), bn1 consts
    for (int i = tid; i < 2048; i += 256) {
        int j = i >> 6, k = i & 63;
        wt[k * 36 + j] = w2[i];
    }
    if (tid < 64) { sc[tid] = g_bn1[tid]; sh[tid] = g_bn1[64 + tid]; }
    float bj[4];
#pragma unroll
    for (int c = 0; c < 4; c++) bj[c] = b2[j0 + c];
    __syncthreads();

    float lsum[4] = {0.f, 0.f, 0.f, 0.f}, lsq[4] = {0.f, 0.f, 0.f, 0.f};

    for (int tile = blockIdx.x; tile < N_TILES; tile += gridDim.x) {
        size_t base = (size_t)tile * TILE_R;
        // stage: bn1 + relu applied, float4 in/out
        for (int i = tid; i < TILE_R * 16; i += 256) {
            int r = i >> 4, c4 = (i & 15) * 4;
            float4 v = *(const float4*)&g_h1[(base + r) * 64 + c4];
            v.x = fmaxf(fmaf(v.x, sc[c4], sh[c4]), 0.f);
            v.y = fmaxf(fmaf(v.y, sc[c4 + 1], sh[c4 + 1]), 0.f);
            v.z = fmaxf(fmaf(v.z, sc[c4 + 2], sh[c4 + 2]), 0.f);
            v.w = fmaxf(fmaf(v.w, sc[c4 + 3], sh[c4 + 3]), 0.f);
            *(float4*)&a[r * 68 + c4] = v;
        }
        __syncthreads();

        float acc[4][4];
#pragma unroll
        for (int i = 0; i < 4; i++)
#pragma unroll
            for (int c = 0; c < 4; c++) acc[i][c] = (i == 0) ? bj[c] : 0.f;

        int rbase = warp * 16 + tr;
#pragma unroll 4
        for (int k = 0; k < 64; k += 4) {
            float4 w0 = *(float4*)&wt[(k + 0) * 36 + j0];
            float4 w1v = *(float4*)&wt[(k + 1) * 36 + j0];
            float4 w2v = *(float4*)&wt[(k + 2) * 36 + j0];
            float4 w3 = *(float4*)&wt[(k + 3) * 36 + j0];
#pragma unroll
            for (int i = 0; i < 4; i++) {
                float4 av = *(float4*)&a[(rbase + i * 4) * 68 + k];
                acc[i][0] = fmaf(av.x, w0.x, acc[i][0]);
                acc[i][1] = fmaf(av.x, w0.y, acc[i][1]);
                acc[i][2] = fmaf(av.x, w0.z, acc[i][2]);
                acc[i][3] = fmaf(av.x, w0.w, acc[i][3]);
                acc[i][0] = fmaf(av.y, w1v.x, acc[i][0]);
                acc[i][1] = fmaf(av.y, w1v.y, acc[i][1]);
                acc[i][2] = fmaf(av.y, w1v.z, acc[i][2]);
                acc[i][3] = fmaf(av.y, w1v.w, acc[i][3]);
                acc[i][0] = fmaf(av.z, w2v.x, acc[i][0]);
                acc[i][1] = fmaf(av.z, w2v.y, acc[i][1]);
                acc[i][2] = fmaf(av.z, w2v.z, acc[i][2]);
                acc[i][3] = fmaf(av.z, w2v.w, acc[i][3]);
                acc[i][0] = fmaf(av.w, w3.x, acc[i][0]);
                acc[i][1] = fmaf(av.w, w3.y, acc[i][1]);
                acc[i][2] = fmaf(av.w, w3.z, acc[i][2]);
                acc[i][3] = fmaf(av.w, w3.w, acc[i][3]);
            }
        }

        // epilogue: rows i>0 need bias too (added only to i==0 above)
#pragma unroll
        for (int i = 1; i < 4; i++)
#pragma unroll
            for (int c = 0; c < 4; c++) acc[i][c] += bj[c];

#pragma unroll
        for (int i = 0; i < 4; i++) {
            size_t r = base + rbase + i * 4;
            float4 o = make_float4(acc[i][0], acc[i][1], acc[i][2], acc[i][3]);
            *(float4*)&g_h2[r * 32 + j0] = o;
#pragma unroll
            for (int c = 0; c < 4; c++) {
                lsum[c] += acc[i][c];
                lsq[c] = fmaf(acc[i][c], acc[i][c], lsq[c]);
            }
        }
        __syncthreads();
    }

    // reduce BN2 partials: over tr (lanes xor 8,16), then across warps
#pragma unroll
    for (int c = 0; c < 4; c++) {
        lsum[c] += __shfl_xor_sync(0xffffffffu, lsum[c], 8);
        lsum[c] += __shfl_xor_sync(0xffffffffu, lsum[c], 16);
        lsq[c] += __shfl_xor_sync(0xffffffffu, lsq[c], 8);
        lsq[c] += __shfl_xor_sync(0xffffffffu, lsq[c], 16);
    }
    if (tr == 0) {
#pragma unroll
        for (int c = 0; c < 4; c++) {
            wsum[warp * 32 + j0 + c] = lsum[c];
            wsq[warp * 32 + j0 + c] = lsq[c];
        }
    }
    __syncthreads();
    int t = tid;
    if (t < 32) {
        float s = 0.f;
#pragma unroll
        for (int w = 0; w < 8; w++) s += wsum[w * 32 + t];
        g_part2[blockIdx.x * 64 + t] = s;
    } else if (t < 64) {
        float q = 0.f;
#pragma unroll
        for (int w = 0; w < 8; w++) q += wsq[w * 32 + (t - 32)];
        g_part2[blockIdx.x * 64 + t] = q;
    }

    __threadfence();
    __shared__ unsigned s_last;
    if (t == 0) {
        unsigned tk = atomicAdd(&g_cnt2, 1u);
        s_last = (tk == gridDim.x - 1) ? 1u : 0u;
    }
    __syncthreads();
    if (s_last) {
        __shared__ float sm[256];
        int ch = t & 63;
        int sl = t >> 6;  // 4 slices of 148
        float aa = 0.f;
        int b0 = sl * (K3_GRID / 4);
        for (int b = b0; b < b0 + K3_GRID / 4; b++) aa += g_part2[b * 64 + ch];
        sm[t] = aa;
        __syncthreads();
        if (t < 32) {
            float s = (sm[t] + sm[64 + t]) + (sm[128 + t] + sm[192 + t]);
            float q = (sm[32 + t] + sm[96 + t]) + (sm[160 + t] + sm[224 + t]);
            float mean = s / (float)NROWS;
            float var = q / (float)NROWS - mean * mean;
            float scale = g2[t] * rsqrtf(var + BN_EPS);
            g_bn2[t] = scale;
            g_bn2[32 + t] = beta2[t] - mean * scale;
        }
        if (t == 0) g_cnt2 = 0;
    }
}

// ---------------------------------------------------------------------------
// Kernel 5: smem-tiled GEMM. out += relu(bn2(h2)) @ w_out^T + b_out.
// ---------------------------------------------------------------------------
__global__ void __launch_bounds__(256) k5(const float* __restrict__ wout,
                                          const float* __restrict__ bout,
                                          float* __restrict__ out) {
    __shared__ float a[TILE_R * 36];     // bn+relu(h2) tile, stride 36
    __shared__ float wt[32 * 36];        // wout transposed: wt[k*36+j]
    __shared__ float sc[32], sh[32];

    int tid = threadIdx.x;
    int lane = tid & 31, warp = tid >> 5;
    int tr = lane >> 3, tj = lane & 7;
    int j0 = tj * 4;

    for (int i = tid; i < 1024; i += 256) {
        int j = i >> 5, k = i & 31;
        wt[k * 36 + j] = wout[i];
    }
    if (tid < 32) { sc[tid] = g_bn2[tid]; sh[tid] = g_bn2[32 + tid]; }
    float bj[4];
#pragma unroll
    for (int c = 0; c < 4; c++) bj[c] = bout[j0 + c];
    __syncthreads();

    for (int tile = blockIdx.x; tile < N_TILES; tile += gridDim.x) {
        size_t base = (size_t)tile * TILE_R;
        for (int i = tid; i < TILE_R * 8; i += 256) {
            int r = i >> 3, c4 = (i & 7) * 4;
            float4 v = *(const float4*)&g_h2[(base + r) * 32 + c4];
            v.x = fmaxf(fmaf(v.x, sc[c4], sh[c4]), 0.f);
            v.y = fmaxf(fmaf(v.y, sc[c4 + 1], sh[c4 + 1]), 0.f);
            v.z = fmaxf(fmaf(v.z, sc[c4 + 2], sh[c4 + 2]), 0.f);
            v.w = fmaxf(fmaf(v.w, sc[c4 + 3], sh[c4 + 3]), 0.f);
            *(float4*)&a[r * 36 + c4] = v;
        }
        __syncthreads();

        float acc[4][4];
#pragma unroll
        for (int i = 0; i < 4; i++)
#pragma unroll
            for (int c = 0; c < 4; c++) acc[i][c] = 0.f;

        int rbase = warp * 16 + tr;
#pragma unroll 4
        for (int k = 0; k < 32; k += 4) {
            float4 w0 = *(float4*)&wt[(k + 0) * 36 + j0];
            float4 w1v = *(float4*)&wt[(k + 1) * 36 + j0];
            float4 w2v = *(float4*)&wt[(k + 2) * 36 + j0];
            float4 w3 = *(float4*)&wt[(k + 3) * 36 + j0];
#pragma unroll
            for (int i = 0; i < 4; i++) {
                float4 av = *(float4*)&a[(rbase + i * 4) * 36 + k];
                acc[i][0] = fmaf(av.x, w0.x, acc[i][0]);
                acc[i][1] = fmaf(av.x, w0.y, acc[i][1]);
                acc[i][2] = fmaf(av.x, w0.z, acc[i][2]);
                acc[i][3] = fmaf(av.x, w0.w, acc[i][3]);
                acc[i][0] = fmaf(av.y, w1v.x, acc[i][0]);
                acc[i][1] = fmaf(av.y, w1v.y, acc[i][1]);
                acc[i][2] = fmaf(av.y, w1v.z, acc[i][2]);
                acc[i][3] = fmaf(av.y, w1v.w, acc[i][3]);
                acc[i][0] = fmaf(av.z, w2v.x, acc[i][0]);
                acc[i][1] = fmaf(av.z, w2v.y, acc[i][1]);
                acc[i][2] = fmaf(av.z, w2v.z, acc[i][2]);
                acc[i][3] = fmaf(av.z, w2v.w, acc[i][3]);
                acc[i][0] = fmaf(av.w, w3.x, acc[i][0]);
                acc[i][1] = fmaf(av.w, w3.y, acc[i][1]);
                acc[i][2] = fmaf(av.w, w3.z, acc[i][2]);
                acc[i][3] = fmaf(av.w, w3.w, acc[i][3]);
            }
        }

#pragma unroll
        for (int i = 0; i < 4; i++) {
            size_t r = base + rbase + i * 4;
            float4 o = *(const float4*)&out[r * 32 + j0];
            o.x += acc[i][0] + bj[0];
            o.y += acc[i][1] + bj[1];
            o.z += acc[i][2] + bj[2];
            o.w += acc[i][3] + bj[3];
            *(float4*)&out[r * 32 + j0] = o;
        }
        __syncthreads();
    }
}

// ---------------------------------------------------------------------------
// Input order (setup_inputs dict insertion): x, emb0, lin0, emb1, lin1,
// emb2, lin2, emb3, lin3, cont_w, cont_b, clin_w, clin_b, fin_bias,
// w1, b1, g1, beta1, w2, b2, g2, beta2, w_out, b_out
// ---------------------------------------------------------------------------
extern "C" void kernel_launch(void* const* d_in, const int* in_sizes, int n_in,
                              void* d_out, int out_size) {
    const float* x      = (const float*)d_in[0];
    const float* emb0   = (const float*)d_in[1];
    const float* lin0   = (const float*)d_in[2];
    const float* emb1   = (const float*)d_in[3];
    const float* lin1   = (const float*)d_in[4];
    const float* emb2   = (const float*)d_in[5];
    const float* lin2   = (const float*)d_in[6];
    const float* emb3   = (const float*)d_in[7];
    const float* lin3   = (const float*)d_in[8];
    const float* cont_w = (const float*)d_in[9];
    const float* cont_b = (const float*)d_in[10];
    const float* clin_w = (const float*)d_in[11];
    const float* clin_b = (const float*)d_in[12];
    const float* fin_b  = (const float*)d_in[13];
    const float* w1     = (const float*)d_in[14];
    const float* b1     = (const float*)d_in[15];
    const float* g1     = (const float*)d_in[16];
    const float* beta1  = (const float*)d_in[17];
    const float* w2     = (const float*)d_in[18];
    const float* b2     = (const float*)d_in[19];
    const float* g2     = (const float*)d_in[20];
    const float* beta2  = (const float*)d_in[21];
    const float* w_out  = (const float*)d_in[22];
    const float* b_out  = (const float*)d_in[23];
    float* out = (float*)d_out;

    kSetup<<<SETUP_BLOCKS, 256>>>(emb0, emb1, emb2, emb3, w1, b1, cont_w, cont_b);
    k1<<<K1_BLOCKS, 256>>>(x, emb0, emb1, emb2, emb3, lin0, lin1, lin2, lin3,
                           cont_w, cont_b, clin_w, clin_b, fin_b, g1, beta1, out);
    k3<<<K3_GRID, 256>>>(w2, b2, g2, beta2);
    k5<<<K5_GRID, 256>>>(w_out, b_out, out);
}